// round 16
// baseline (speedup 1.0000x reference)
#include <cuda_runtime.h>
#include <cstddef>
#include <cstdint>

// CTC loss forward. B=32, T=800, C=5000, L=100, S=201.
//
// R15 = R14 (shfl/halo/window alpha + dense emit gather) with TWO time steps
// per exchange point: R11's exact pair trick (redundant recompute of the
// neighbor's odd state at t+1 from lanes l-1/l-2) layered on the shfl
// exchange. Rationale: R11 (bar/2 steps) and R14 (bar/6 steps) ran the SAME
// 82us alpha -> the bottleneck is the per-step shfl+LAE dependent chain, not
// barriers. Pairing halves the number of 26-cyc shfl waits per step.
// Window = 6 steps = 3 pairs; contamination 2 lanes/pair x 3 = 6 = halo. ✓
// Boundary: publish raw (b,s); renorm overlaps the barrier wait.

#define Bb 32
#define Tt 800
#define Cc 5000
#define Ll 100
#define EP 128            // emit row stride (floats), line-aligned
#define NEGV (-1e30f)
#define LOG2E 1.4426950408889634f
#define LN2   0.6931471805599453f
#define W 6               // window length (steps) == halo depth
#define NP 3              // pairs per window
#define NTHR 128

__device__ float    g_emit[(size_t)Bb * Tt * EP];
__device__ float    g_tot[Bb];
__device__ unsigned g_done;          // self-resetting

__device__ __forceinline__ float ex2f(float x) {
    float y; asm("ex2.approx.ftz.f32 %0, %1;" : "=f"(y) : "f"(x)); return y;
}
__device__ __forceinline__ float lg2f(float x) {
    float y; asm("lg2.approx.ftz.f32 %0, %1;" : "=f"(y) : "f"(x)); return y;
}

// (base,sum) logaddexp combine: (bx,sx) (+) (by,sy) -> (mb, ms), single ex2.
#define LAE(bx, sx, by, sy, mb, ms)                                        \
    {                                                                      \
        float d_ = __fadd_rn(bx, -(by));                                   \
        float u_ = ex2f(fminf(d_, -d_));                                   \
        mb = fmaxf(bx, by);                                                \
        ms = (d_ >= 0.f) ? __fmaf_rn(sy, u_, sx) : __fmaf_rn(sx, u_, sy);  \
    }

// Single time step (remainder path). Contamination 1 lane/step.
#define STEP(ecb, eco)                                                     \
    {                                                                      \
        float nbz = __shfl_up_sync(0xffffffffu, bo, 1);                    \
        float nbw = __shfl_up_sync(0xffffffffu, so, 1);                    \
        float mA, sA; LAE(be, se, nbz, nbw, mA, sA);                       \
        float m1, s1; LAE(bo, so, be, se, m1, s1);                         \
        float bz = skip ? nbz : NEGV, wz = skip ? nbw : 0.f;               \
        float mC, sC; LAE(m1, s1, bz, wz, mC, sC);                         \
        be = __fadd_rn(mA, (ecb)); se = sA;                                \
        bo = __fadd_rn(mC, (eco)); so = sC;                                \
    }

// Two time steps per exchange: 6 batched shfls, then register-only compute.
// Redundantly recomputes neighbor (l-1)'s odd state at t+1 (exact math,
// identical expression structure to the primary path).
#define PAIR(e1b, e1o, e1p, e2b, e2o)                                      \
    {                                                                      \
        float n1x = __shfl_up_sync(0xffffffffu, be, 1);                    \
        float n1y = __shfl_up_sync(0xffffffffu, se, 1);                    \
        float n1z = __shfl_up_sync(0xffffffffu, bo, 1);                    \
        float n1w = __shfl_up_sync(0xffffffffu, so, 1);                    \
        float n2z = __shfl_up_sync(0xffffffffu, bo, 2);                    \
        float n2w = __shfl_up_sync(0xffffffffu, so, 2);                    \
        /* redundant: neighbor's odd @ t+1 */                              \
        float mR1, sR1; LAE(n1z, n1w, n1x, n1y, mR1, sR1);                 \
        float bzR = skipP ? n2z : NEGV, wzR = skipP ? n2w : 0.f;           \
        float mRP, sP;  LAE(mR1, sR1, bzR, wzR, mRP, sP);                  \
        float bP = __fadd_rn(mRP, (e1p));                                  \
        /* own step t+1 */                                                 \
        float mA, sA; LAE(be, se, n1z, n1w, mA, sA);                       \
        float m1, s1; LAE(bo, so, be, se, m1, s1);                         \
        float bzB = skip ? n1z : NEGV, wzB = skip ? n1w : 0.f;             \
        float mC, sC; LAE(m1, s1, bzB, wzB, mC, sC);                       \
        float be1 = __fadd_rn(mA, (e1b)), se1 = sA;                        \
        float bo1 = __fadd_rn(mC, (e1o)), so1 = sC;                        \
        /* own step t+2 (neighbor odd = (bP,sP)) */                        \
        float mD, sD; LAE(be1, se1, bP, sP, mD, sD);                       \
        float mE, sE; LAE(bo1, so1, be1, se1, mE, sE);                     \
        float bzF = skip ? bP : NEGV, wzF = skip ? sP : 0.f;               \
        float mF, sF; LAE(mE, sE, bzF, wzF, mF, sF);                       \
        be = __fadd_rn(mD, (e2b)); se = sD;                                \
        bo = __fadd_rn(mF, (e2o)); so = sF;                                \
    }

// ---------------------------------------------------------------------------
// Kernel 1: gather (full chip). emit[bt][j] = LOG2E * lp[bt, col(j)].
// ---------------------------------------------------------------------------
__global__ void gather_kernel(const float* __restrict__ lp,
                              const int* __restrict__ targets,
                              const int* __restrict__ ilen) {
    int idx = blockIdx.x * blockDim.x + threadIdx.x;
    const int total = Bb * Tt * (Ll + 1);
    if (idx >= total) return;
    int j  = idx % (Ll + 1);
    int bt = idx / (Ll + 1);
    int b  = bt / Tt;
    int t  = bt - b * Tt;
    if (t >= ilen[b]) return;
    int c = (j == 0) ? 0 : targets[b * Ll + (j - 1)];
    g_emit[(size_t)bt * EP + j] = LOG2E * __ldg(lp + (size_t)bt * Cc + c);
}

// ---------------------------------------------------------------------------
// Kernel 2: paired shfl-windowed alpha + fused reduction. grid=B, 128 thr.
// ---------------------------------------------------------------------------
__global__ __launch_bounds__(NTHR, 1)
void ctc_alpha(const int* __restrict__ targets,
               const int* __restrict__ ilen,
               const int* __restrict__ tlen,
               float* __restrict__ out)
{
    // pub[buf][slot+6]; indices 0..5 are permanent left-boundary pads.
    __shared__ float4 pub[2][110];
    __shared__ int s_lastflag;

    const int b = blockIdx.x;
    const int i = threadIdx.x;
    const int w = i >> 5;
    const int l = i & 31;
    const int slot = 26 * w - 6 + l;     // -6 .. 103
    const int last = ilen[b] - 1;        // >= 599 for this problem

    // Static params. Own odd state = 2*slot+1 (class targets[slot]); the
    // redundant path needs neighbor's skip flag and emission column too.
    const int tgR   = (slot >= 0 && slot < Ll)      ? targets[b * Ll + slot]     : 0;
    const int tgpR  = (slot >= 1 && slot <= Ll)     ? targets[b * Ll + slot - 1] : -1;
    const int tgppR = (slot >= 2 && slot <= Ll + 1) ? targets[b * Ll + slot - 2] : -1;
    const bool skip  = (tgR  != tgpR);
    const bool skipP = (tgpR != tgppR);
    const int jo = (slot >= 0 && slot < Ll)  ? slot + 1 : 0;  // own odd col
    const int jp = (slot >= 1 && slot <= Ll) ? slot     : 0;  // neighbor odd col

    const float* __restrict__ em = g_emit + (size_t)b * Tt * EP;

    if (i < W) {                         // left pads, both buffers, once
        pub[0][i] = make_float4(NEGV, 1.f, NEGV, 1.f);
        pub[1][i] = make_float4(NEGV, 1.f, NEGV, 1.f);
    }

    // t=0 init (log2 domain, alpha = base + lg2(sum)); only slot 0 live.
    float se = 1.f, so = 1.f;
    float be = (slot == 0) ? em[0]  : NEGV;
    float bo = (slot == 0) ? em[jo] : NEGV;

    __syncthreads();                     // pads visible before first reload

    // Prefetch rings for window 0 (steps 1..6 = pairs 0..2), literal idx.
    float r1b[NP], r1o[NP], r1p[NP], r2b[NP], r2o[NP];
#pragma unroll
    for (int u = 0; u < NP; ++u) {
        int t1 = 2 * u + 1; if (t1 > last) t1 = last;
        int t2 = 2 * u + 2; if (t2 > last) t2 = last;
        r1b[u] = em[(size_t)t1 * EP];
        r1o[u] = em[(size_t)t1 * EP + jo];
        r1p[u] = em[(size_t)t1 * EP + jp];
        r2b[u] = em[(size_t)t2 * EP];
        r2o[u] = em[(size_t)t2 * EP + jo];
    }

    const int nwin = last / W;           // full windows (steps 1..nwin*W)
    int buf = 0;

    for (int n = 0; n < nwin; ++n) {
        const int tw = n * W;            // window covers steps tw+1..tw+6
#pragma unroll
        for (int u = 0; u < NP; ++u) {   // u literal -> rings in registers
            const float e1b = r1b[u], e1o = r1o[u], e1p = r1p[u];
            const float e2b = r2b[u], e2o = r2o[u];
            int q1 = tw + W + 2 * u + 1; if (q1 > last) q1 = last;
            int q2 = q1 + 1;             if (q2 > last) q2 = last;
            r1b[u] = em[(size_t)q1 * EP];
            r1o[u] = em[(size_t)q1 * EP + jo];
            r1p[u] = em[(size_t)q1 * EP + jp];
            r2b[u] = em[(size_t)q2 * EP];
            r2o[u] = em[(size_t)q2 * EP + jo];
            PAIR(e1b, e1o, e1p, e2b, e2o);
        }
        // Boundary: publish RAW pairs first; renorm overlaps the barrier.
        buf ^= 1;
        if (l >= W) pub[buf][slot + 6] = make_float4(be, se, bo, so);
        be = fmaxf(be + lg2f(se), NEGV); se = 1.f;
        bo = fmaxf(bo + lg2f(so), NEGV); so = 1.f;
        __syncthreads();
        if (l < W) {                     // halo reload + identical renorm
            float4 v = pub[buf][slot + 6];
            be = fmaxf(v.x + lg2f(v.y), NEGV); se = 1.f;
            bo = fmaxf(v.z + lg2f(v.w), NEGV); so = 1.f;
        }
    }

    // Remainder steps (<= 5): direct loads, single-step shfl updates;
    // contamination depth <= 5 stays inside the 6-lane halo.
    for (int t = nwin * W + 1; t <= last; ++t) {
        const float ecb = em[(size_t)t * EP];
        const float eco = em[(size_t)t * EP + jo];
        STEP(ecb, eco);
    }

    // Final fold + publish output lanes.
    be = fmaxf(be + lg2f(se), NEGV);
    bo = fmaxf(bo + lg2f(so), NEGV);
    buf ^= 1;
    if (l >= W) pub[buf][slot + 6] = make_float4(be, 1.f, bo, 1.f);
    __syncthreads();

    if (i == 0) {
        int Lb = tlen[b];
        float x = pub[buf][Lb + 6].x;        // even state 2Lb   (slot Lb)
        float y = pub[buf][Lb - 1 + 6].z;    // odd  state 2Lb-1 (slot Lb-1)
        float m = fmaxf(x, y);
        g_tot[b] = LN2 * (m + lg2f(ex2f(x - m) + ex2f(y - m)));
        __threadfence();
        unsigned v = atomicAdd(&g_done, 1u);
        s_lastflag = (v == Bb - 1u) ? 1 : 0;
    }
    __syncthreads();

    if (s_lastflag && i < 32) {              // last block: fused reduction
        __threadfence();
        float tot = g_tot[i];
        float il  = (float)ilen[i];
        bool  ok  = tot > NEGV * 0.5f;
        float tsum = ok ? tot : 0.f;
        float tf   = ok ? il  : 0.f;
        float af   = il;
#pragma unroll
        for (int s = 16; s >= 1; s >>= 1) {
            tsum += __shfl_down_sync(0xFFFFFFFFu, tsum, s);
            tf   += __shfl_down_sync(0xFFFFFFFFu, tf, s);
            af   += __shfl_down_sync(0xFFFFFFFFu, af, s);
        }
        if (i == 0) {
            out[0] = tsum; out[1] = tf; out[2] = af;
            g_done = 0;                      // reset for next graph replay
        }
    }
}

// ---------------------------------------------------------------------------
extern "C" void kernel_launch(void* const* d_in, const int* in_sizes, int n_in,
                              void* d_out, int out_size) {
    const float* lp      = (const float*)d_in[0];  // nnet_output [B,T,C] f32
    const int*   targets = (const int*)  d_in[1];  // [B,L] i32
    const int*   ilen    = (const int*)  d_in[2];  // [B] i32
    const int*   tlen    = (const int*)  d_in[3];  // [B] i32

    const int total = Bb * Tt * (Ll + 1);
    gather_kernel<<<(total + 255) / 256, 256>>>(lp, targets, ilen);
    ctc_alpha<<<Bb, NTHR>>>(targets, ilen, tlen, (float*)d_out);
}